// round 1
// baseline (speedup 1.0000x reference)
#include <cuda_runtime.h>

// ---------------- problem constants ----------------
#define NSENT   4000
#define LSEQ    128
#define VOCAB   50002
#define VEC_DIM 50
#define POS_DIM 5
#define EMB     60
#define HID     230
#define PADC    240            // HID padded to 240 (float4-friendly)
#define ROWW    (3*PADC)       // 720 floats per table row (3 kernel taps)
#define NPOS    201
#define NBAG    500
#define NREL    25

// ---------------- device scratch (static; no runtime allocation) ----------------
__device__ float g_B  [VEC_DIM * ROWW];            // transposed word-part weights [50][720]
__device__ float g_Tw [(size_t)VOCAB * ROWW];      // word projection table  (~144 MB)
__device__ float g_Tp1[NPOS * ROWW];               // pos1 projection table
__device__ float g_Tp2[NPOS * ROWW];               // pos2 projection table
__device__ float g_H  [NSENT * PADC];              // sentence encodings (post max-pool/relu)

// ---------------- helpers ----------------
__device__ __forceinline__ float4 ld4(const float* p) { return *reinterpret_cast<const float4*>(p); }
__device__ __forceinline__ float4 add4(float4 a, float4 b) {
    return make_float4(a.x+b.x, a.y+b.y, a.z+b.z, a.w+b.w);
}
__device__ __forceinline__ float4 max4(float4 a, float4 b) {
    return make_float4(fmaxf(a.x,b.x), fmaxf(a.y,b.y), fmaxf(a.z,b.z), fmaxf(a.w,b.w));
}

// ---------------- kernel 1: transpose conv_w word-part into g_B ----------------
// g_B[e*ROWW + k*PADC + c] = conv_w[c][e][k]  (c<HID), else 0
__global__ void k_prep_B(const float* __restrict__ conv_w) {
    int i = blockIdx.x * blockDim.x + threadIdx.x;
    if (i >= VEC_DIM * ROWW) return;
    int e = i / ROWW;
    int r = i - e * ROWW;
    int k = r / PADC;
    int c = r - k * PADC;
    g_B[i] = (c < HID) ? conv_w[(c * EMB + e) * 3 + k] : 0.f;
}

// ---------------- kernel 2: tiny pos tables (K=5) ----------------
__global__ void k_pos_tables(const float* __restrict__ p1e,
                             const float* __restrict__ p2e,
                             const float* __restrict__ conv_w) {
    int p = blockIdx.x;        // 0..200
    int r = threadIdx.x;       // 0..719
    int k = r / PADC;
    int c = r - k * PADC;
    float a1 = 0.f, a2 = 0.f;
    if (c < HID) {
        #pragma unroll
        for (int e = 0; e < POS_DIM; e++) {
            float w1 = conv_w[(c * EMB + VEC_DIM + e) * 3 + k];
            float w2 = conv_w[(c * EMB + VEC_DIM + POS_DIM + e) * 3 + k];
            a1 = fmaf(p1e[p * POS_DIM + e], w1, a1);
            a2 = fmaf(p2e[p * POS_DIM + e], w2, a2);
        }
    }
    g_Tp1[p * ROWW + r] = a1;
    g_Tp2[p * ROWW + r] = a2;
}

// ---------------- kernel 3: word table build GEMM  [VOCAB,50] x [50,720] ----------------
// block = 192 threads (180 active, 4 cols each), 32 vocab rows per block (4 chunks of 8)
__global__ __launch_bounds__(192) void k_build_word(const float* __restrict__ word_emb) {
    __shared__ float s_emb[32][VEC_DIM];
    int row0 = blockIdx.x * 32;
    for (int i = threadIdx.x; i < 32 * VEC_DIM; i += blockDim.x) {
        int r = i / VEC_DIM, e = i - r * VEC_DIM;
        int gr = row0 + r;
        s_emb[r][e] = (gr < VOCAB) ? word_emb[gr * VEC_DIM + e] : 0.f;
    }
    __syncthreads();
    int t = threadIdx.x;
    if (t >= 180) return;
    int col = t * 4;
    #pragma unroll
    for (int chunk = 0; chunk < 4; chunk++) {
        int rbase = chunk * 8;
        float acc[8][4];
        #pragma unroll
        for (int r = 0; r < 8; r++)
            acc[r][0] = acc[r][1] = acc[r][2] = acc[r][3] = 0.f;
        for (int e = 0; e < VEC_DIM; e++) {
            float4 b = ld4(&g_B[e * ROWW + col]);
            #pragma unroll
            for (int r = 0; r < 8; r++) {
                float a = s_emb[rbase + r][e];
                acc[r][0] = fmaf(a, b.x, acc[r][0]);
                acc[r][1] = fmaf(a, b.y, acc[r][1]);
                acc[r][2] = fmaf(a, b.z, acc[r][2]);
                acc[r][3] = fmaf(a, b.w, acc[r][3]);
            }
        }
        #pragma unroll
        for (int r = 0; r < 8; r++) {
            int gr = row0 + rbase + r;
            if (gr < VOCAB) {
                float4 v = make_float4(acc[r][0], acc[r][1], acc[r][2], acc[r][3]);
                *reinterpret_cast<float4*>(&g_Tw[(size_t)gr * ROWW + col]) = v;
            }
        }
    }
}

// ---------------- kernel 4: main fused conv-via-gather + maxpool + relu ----------------
// block = 256 threads = 4 sentences x 64 lanes; lane tc<60 owns 4 channels (float4)
__global__ __launch_bounds__(256) void k_main(const int* __restrict__ X,
                                              const int* __restrict__ P1,
                                              const int* __restrict__ P2,
                                              const float* __restrict__ conv_b) {
    __shared__ int   s_idx[4][3][LSEQ];
    __shared__ float s_b[PADC];
    int tid = threadIdx.x;
    int grp = tid >> 6, tc = tid & 63;
    int sent0 = blockIdx.x * 4;

    for (int i = tid; i < 4 * LSEQ; i += 256) {
        int g = i >> 7, t = i & (LSEQ - 1);
        int s = sent0 + g;
        s_idx[g][0][t] = X [s * LSEQ + t];
        s_idx[g][1][t] = P1[s * LSEQ + t];
        s_idx[g][2][t] = P2[s * LSEQ + t];
    }
    if (tid < PADC) s_b[tid] = (tid < HID) ? conv_b[tid] : 0.f;
    __syncthreads();

    if (tc >= 60) return;
    int coff = tc * 4;

    float4 maxv  = make_float4(-1e30f, -1e30f, -1e30f, -1e30f);
    float4 pend  = make_float4(0.f, 0.f, 0.f, 0.f);   // a0(t-1)+a1(t) carried forward
    float4 prev0 = make_float4(0.f, 0.f, 0.f, 0.f);   // a0 of previous token

    for (int t = 0; t < LSEQ; t++) {
        const float* rw = g_Tw  + (size_t)s_idx[grp][0][t] * ROWW + coff;
        const float* r1 = g_Tp1 + (size_t)s_idx[grp][1][t] * ROWW + coff;
        const float* r2 = g_Tp2 + (size_t)s_idx[grp][2][t] * ROWW + coff;
        float4 w0 = ld4(rw);            float4 w1 = ld4(rw + PADC);  float4 w2 = ld4(rw + 2*PADC);
        float4 q0 = ld4(r1);            float4 q1 = ld4(r1 + PADC);  float4 q2 = ld4(r1 + 2*PADC);
        float4 v0 = ld4(r2);            float4 v1 = ld4(r2 + PADC);  float4 v2 = ld4(r2 + 2*PADC);

        float4 a0 = add4(add4(w0, q0), v0);
        float4 a1 = add4(add4(w1, q1), v1);
        float4 a2 = add4(add4(w2, q2), v2);

        if (t > 0) {                      // finalize h[t-1] = a0(t-2)+a1(t-1)+a2(t)
            float4 h = add4(pend, a2);
            maxv = max4(maxv, h);
        }
        pend  = add4(prev0, a1);
        prev0 = a0;
    }
    maxv = max4(maxv, pend);              // h[L-1] (a2 of token L is zero pad)

    int s = sent0 + grp;
    float b0 = s_b[coff + 0], b1 = s_b[coff + 1], b2 = s_b[coff + 2], b3 = s_b[coff + 3];
    g_H[s * PADC + coff + 0] = fmaxf(maxv.x + b0, 0.f);
    g_H[s * PADC + coff + 1] = fmaxf(maxv.y + b1, 0.f);
    g_H[s * PADC + coff + 2] = fmaxf(maxv.z + b2, 0.f);
    g_H[s * PADC + coff + 3] = fmaxf(maxv.w + b3, 0.f);
}

// ---------------- kernel 5: per-bag softmax attention + classifier ----------------
__global__ __launch_bounds__(256) void k_bags(const int* __restrict__ scope,
                                              const int* __restrict__ relation,
                                              const float* __restrict__ rel_w,
                                              const float* __restrict__ rel_b,
                                              float* __restrict__ out) {
    int b = blockIdx.x;
    __shared__ float s_q[HID];
    __shared__ float s_logit[8];
    __shared__ float s_alpha[8];
    __shared__ float s_rep[HID];

    int tid = threadIdx.x;
    int w = tid >> 5, lane = tid & 31;
    int s0 = scope[2 * b], s1 = scope[2 * b + 1];
    int sz = s1 - s0;                         // == 8 here
    if (sz > 8) sz = 8;
    int rq = relation[b];

    for (int c = tid; c < HID; c += 256) s_q[c] = rel_w[rq * HID + c];
    __syncthreads();

    if (w < 8) {
        float acc = 0.f;
        if (w < sz) {
            const float* hp = g_H + (size_t)(s0 + w) * PADC;
            for (int c = lane; c < HID; c += 32) acc = fmaf(hp[c], s_q[c], acc);
        }
        #pragma unroll
        for (int o = 16; o; o >>= 1) acc += __shfl_xor_sync(0xffffffffu, acc, o);
        if (lane == 0) s_logit[w] = (w < sz) ? acc : -1e30f;
    }
    __syncthreads();

    if (tid == 0) {
        float m = -1e30f;
        for (int i = 0; i < sz; i++) m = fmaxf(m, s_logit[i]);
        float d = 0.f;
        for (int i = 0; i < sz; i++) { float e = expf(s_logit[i] - m); s_alpha[i] = e; d += e; }
        float inv = 1.f / d;
        for (int i = 0; i < sz; i++) s_alpha[i] *= inv;
    }
    __syncthreads();

    for (int c = tid; c < HID; c += 256) {
        float acc = 0.f;
        for (int i = 0; i < sz; i++)
            acc = fmaf(s_alpha[i], g_H[(size_t)(s0 + i) * PADC + c], acc);
        s_rep[c] = acc;
    }
    __syncthreads();

    for (int rr = w; rr < NREL; rr += 8) {
        float acc = 0.f;
        for (int c = lane; c < HID; c += 32) acc = fmaf(s_rep[c], rel_w[rr * HID + c], acc);
        #pragma unroll
        for (int o = 16; o; o >>= 1) acc += __shfl_xor_sync(0xffffffffu, acc, o);
        if (lane == 0) out[b * NREL + rr] = acc + rel_b[rr];
    }
}

// ---------------- launch ----------------
extern "C" void kernel_launch(void* const* d_in, const int* in_sizes, int n_in,
                              void* d_out, int out_size) {
    const int*   X        = (const int*)  d_in[0];
    const int*   P1       = (const int*)  d_in[1];
    const int*   P2       = (const int*)  d_in[2];
    // d_in[3] mask, d_in[4] length: unused
    const int*   scope    = (const int*)  d_in[5];
    const int*   relation = (const int*)  d_in[6];
    const float* word_emb = (const float*)d_in[7];
    const float* p1e      = (const float*)d_in[8];
    const float* p2e      = (const float*)d_in[9];
    const float* conv_w   = (const float*)d_in[10];
    const float* conv_b   = (const float*)d_in[11];
    const float* rel_w    = (const float*)d_in[12];
    const float* rel_b    = (const float*)d_in[13];
    float* out = (float*)d_out;

    k_prep_B<<<(VEC_DIM * ROWW + 255) / 256, 256>>>(conv_w);
    k_pos_tables<<<NPOS, ROWW>>>(p1e, p2e, conv_w);
    k_build_word<<<(VOCAB + 31) / 32, 192>>>(word_emb);
    k_main<<<NSENT / 4, 256>>>(X, P1, P2, conv_b);
    k_bags<<<NBAG, 256>>>(scope, relation, rel_w, rel_b, out);
}

// round 2
// speedup vs baseline: 1.1891x; 1.1891x over previous
#include <cuda_runtime.h>
#include <cuda_fp16.h>

// ---------------- problem constants ----------------
#define NSENT   4000
#define LSEQ    128
#define VOCAB   50002
#define VEC_DIM 50
#define POS_DIM 5
#define EMB     60
#define HID     230
#define PADC    240            // HID padded to 240 (float4-friendly)
#define ROWW    (3*PADC)       // 720 entries per table row (3 kernel taps)
#define NPOS    201
#define NBAG    500
#define NREL    25

// ---------------- device scratch (static; no runtime allocation) ----------------
__device__ float  g_B  [VEC_DIM * ROWW];           // transposed word-part weights [50][720]
__device__ __half g_Tw [(size_t)VOCAB * ROWW];     // word projection table (fp16, ~72 MB: L2-resident)
__device__ float  g_Tp1[NPOS * ROWW];              // pos1 projection table (fp32)
__device__ float  g_Tp2[NPOS * ROWW];              // pos2 projection table (fp32)
__device__ float  g_H  [NSENT * PADC];             // sentence encodings (post max-pool/relu)

// ---------------- helpers ----------------
__device__ __forceinline__ float4 ld4(const float* p) { return *reinterpret_cast<const float4*>(p); }
__device__ __forceinline__ float4 add4(float4 a, float4 b) {
    return make_float4(a.x+b.x, a.y+b.y, a.z+b.z, a.w+b.w);
}
__device__ __forceinline__ float4 max4(float4 a, float4 b) {
    return make_float4(fmaxf(a.x,b.x), fmaxf(a.y,b.y), fmaxf(a.z,b.z), fmaxf(a.w,b.w));
}
// load 4 halfs (8B) and widen to float4
__device__ __forceinline__ float4 ldh4f(const __half* p) {
    uint2 u = *reinterpret_cast<const uint2*>(p);
    __half2 lo = *reinterpret_cast<__half2*>(&u.x);
    __half2 hi = *reinterpret_cast<__half2*>(&u.y);
    float2 f0 = __half22float2(lo);
    float2 f1 = __half22float2(hi);
    return make_float4(f0.x, f0.y, f1.x, f1.y);
}

// packed f32x2 FMA: d = a*b + d   (a,b,d are b64 holding 2 packed fp32)
#define FMA2(d, a, b) \
    asm("fma.rn.f32x2 %0, %1, %2, %3;" : "=l"(d) : "l"(a), "l"(b), "l"(d))

// ---------------- kernel 1: transpose conv_w word-part into g_B ----------------
__global__ void k_prep_B(const float* __restrict__ conv_w) {
    int i = blockIdx.x * blockDim.x + threadIdx.x;
    if (i >= VEC_DIM * ROWW) return;
    int e = i / ROWW;
    int r = i - e * ROWW;
    int k = r / PADC;
    int c = r - k * PADC;
    g_B[i] = (c < HID) ? conv_w[(c * EMB + e) * 3 + k] : 0.f;
}

// ---------------- kernel 2: tiny pos tables (K=5, fp32 out) ----------------
__global__ void k_pos_tables(const float* __restrict__ p1e,
                             const float* __restrict__ p2e,
                             const float* __restrict__ conv_w) {
    int p = blockIdx.x;        // 0..200
    int r = threadIdx.x;       // 0..719
    int k = r / PADC;
    int c = r - k * PADC;
    float a1 = 0.f, a2 = 0.f;
    if (c < HID) {
        #pragma unroll
        for (int e = 0; e < POS_DIM; e++) {
            float w1 = conv_w[(c * EMB + VEC_DIM + e) * 3 + k];
            float w2 = conv_w[(c * EMB + VEC_DIM + POS_DIM + e) * 3 + k];
            a1 = fmaf(p1e[p * POS_DIM + e], w1, a1);
            a2 = fmaf(p2e[p * POS_DIM + e], w2, a2);
        }
    }
    g_Tp1[p * ROWW + r] = a1;
    g_Tp2[p * ROWW + r] = a2;
}

// ---------------- kernel 3: word table build GEMM (f32x2 packed, fp16 out) ----------------
// [VOCAB,50] x [50,720] -> fp16 table. 192 threads (180 active, 4 cols each),
// 32 vocab rows per block in 4 chunks of 8. A-scalars pre-replicated into packed b64.
__global__ __launch_bounds__(192) void k_build_word(const float* __restrict__ word_emb) {
    __shared__ unsigned long long s_a[32][VEC_DIM];   // (a,a) packed pairs
    int row0 = blockIdx.x * 32;
    for (int i = threadIdx.x; i < 32 * VEC_DIM; i += blockDim.x) {
        int r = i / VEC_DIM, e = i - r * VEC_DIM;
        int gr = row0 + r;
        float v = (gr < VOCAB) ? word_emb[gr * VEC_DIM + e] : 0.f;
        unsigned bi = __float_as_uint(v);
        s_a[r][e] = ((unsigned long long)bi << 32) | (unsigned long long)bi;
    }
    __syncthreads();
    int t = threadIdx.x;
    if (t >= 180) return;
    int col = t * 4;
    #pragma unroll
    for (int chunk = 0; chunk < 4; chunk++) {
        int rbase = chunk * 8;
        unsigned long long acc[8][2];
        #pragma unroll
        for (int r = 0; r < 8; r++) { acc[r][0] = 0ULL; acc[r][1] = 0ULL; }
        for (int e = 0; e < VEC_DIM; e++) {
            ulonglong2 b = *reinterpret_cast<const ulonglong2*>(&g_B[e * ROWW + col]);
            #pragma unroll
            for (int r = 0; r < 8; r++) {
                unsigned long long a = s_a[rbase + r][e];
                FMA2(acc[r][0], a, b.x);
                FMA2(acc[r][1], a, b.y);
            }
        }
        #pragma unroll
        for (int r = 0; r < 8; r++) {
            int gr = row0 + rbase + r;
            if (gr < VOCAB) {
                float lo0, hi0, lo1, hi1;
                asm("mov.b64 {%0, %1}, %2;" : "=f"(lo0), "=f"(hi0) : "l"(acc[r][0]));
                asm("mov.b64 {%0, %1}, %2;" : "=f"(lo1), "=f"(hi1) : "l"(acc[r][1]));
                __half2 h01 = __floats2half2_rn(lo0, hi0);
                __half2 h23 = __floats2half2_rn(lo1, hi1);
                uint2 st;
                st.x = *reinterpret_cast<unsigned*>(&h01);
                st.y = *reinterpret_cast<unsigned*>(&h23);
                *reinterpret_cast<uint2*>(&g_Tw[(size_t)gr * ROWW + col]) = st;
            }
        }
    }
}

// ---------------- kernel 4: main fused conv-via-gather + maxpool + relu ----------------
// block = 128 threads = 2 sentences x 64 lanes; lane tc<60 owns 4 channels
__global__ __launch_bounds__(128) void k_main(const int* __restrict__ X,
                                              const int* __restrict__ P1,
                                              const int* __restrict__ P2,
                                              const float* __restrict__ conv_b) {
    __shared__ int   s_idx[2][3][LSEQ];
    __shared__ float s_b[PADC];
    int tid = threadIdx.x;
    int grp = tid >> 6, tc = tid & 63;
    int sent0 = blockIdx.x * 2;

    for (int i = tid; i < 2 * LSEQ; i += 128) {
        int g = i >> 7, t = i & (LSEQ - 1);
        int s = sent0 + g;
        s_idx[g][0][t] = X [s * LSEQ + t];
        s_idx[g][1][t] = P1[s * LSEQ + t];
        s_idx[g][2][t] = P2[s * LSEQ + t];
    }
    for (int i = tid; i < PADC; i += 128) s_b[i] = (i < HID) ? conv_b[i] : 0.f;
    __syncthreads();

    if (tc >= 60) return;
    int coff = tc * 4;

    const int* xw = s_idx[grp][0];
    const int* x1 = s_idx[grp][1];
    const int* x2 = s_idx[grp][2];

    float4 maxv  = make_float4(-1e30f, -1e30f, -1e30f, -1e30f);
    float4 pend  = make_float4(0.f, 0.f, 0.f, 0.f);   // a0(t-1)+a1(t) carried forward
    float4 prev0 = make_float4(0.f, 0.f, 0.f, 0.f);   // a0 of previous token

    #pragma unroll 2
    for (int t = 0; t < LSEQ; t++) {
        const __half* rw = g_Tw  + (size_t)xw[t] * ROWW + coff;
        const float*  r1 = g_Tp1 + (size_t)x1[t] * ROWW + coff;
        const float*  r2 = g_Tp2 + (size_t)x2[t] * ROWW + coff;
        float4 w0 = ldh4f(rw);  float4 w1 = ldh4f(rw + PADC);  float4 w2 = ldh4f(rw + 2*PADC);
        float4 q0 = ld4(r1);    float4 q1 = ld4(r1 + PADC);    float4 q2 = ld4(r1 + 2*PADC);
        float4 v0 = ld4(r2);    float4 v1 = ld4(r2 + PADC);    float4 v2 = ld4(r2 + 2*PADC);

        float4 a0 = add4(add4(w0, q0), v0);
        float4 a1 = add4(add4(w1, q1), v1);
        float4 a2 = add4(add4(w2, q2), v2);

        if (t > 0) {                      // finalize h[t-1] = a0(t-2)+a1(t-1)+a2(t)
            float4 h = add4(pend, a2);
            maxv = max4(maxv, h);
        }
        pend  = add4(prev0, a1);
        prev0 = a0;
    }
    maxv = max4(maxv, pend);              // h[L-1] (a2 of token L is zero pad)

    int s = sent0 + grp;
    g_H[s * PADC + coff + 0] = fmaxf(maxv.x + s_b[coff + 0], 0.f);
    g_H[s * PADC + coff + 1] = fmaxf(maxv.y + s_b[coff + 1], 0.f);
    g_H[s * PADC + coff + 2] = fmaxf(maxv.z + s_b[coff + 2], 0.f);
    g_H[s * PADC + coff + 3] = fmaxf(maxv.w + s_b[coff + 3], 0.f);
}

// ---------------- kernel 5: per-bag softmax attention + classifier ----------------
__global__ __launch_bounds__(256) void k_bags(const int* __restrict__ scope,
                                              const int* __restrict__ relation,
                                              const float* __restrict__ rel_w,
                                              const float* __restrict__ rel_b,
                                              float* __restrict__ out) {
    int b = blockIdx.x;
    __shared__ float s_q[HID];
    __shared__ float s_logit[8];
    __shared__ float s_alpha[8];
    __shared__ float s_rep[HID];

    int tid = threadIdx.x;
    int w = tid >> 5, lane = tid & 31;
    int s0 = scope[2 * b], s1 = scope[2 * b + 1];
    int sz = s1 - s0;                         // == 8 here
    if (sz > 8) sz = 8;
    int rq = relation[b];

    for (int c = tid; c < HID; c += 256) s_q[c] = rel_w[rq * HID + c];
    __syncthreads();

    if (w < 8) {
        float acc = 0.f;
        if (w < sz) {
            const float* hp = g_H + (size_t)(s0 + w) * PADC;
            for (int c = lane; c < HID; c += 32) acc = fmaf(hp[c], s_q[c], acc);
        }
        #pragma unroll
        for (int o = 16; o; o >>= 1) acc += __shfl_xor_sync(0xffffffffu, acc, o);
        if (lane == 0) s_logit[w] = (w < sz) ? acc : -1e30f;
    }
    __syncthreads();

    if (tid == 0) {
        float m = -1e30f;
        for (int i = 0; i < sz; i++) m = fmaxf(m, s_logit[i]);
        float d = 0.f;
        for (int i = 0; i < sz; i++) { float e = expf(s_logit[i] - m); s_alpha[i] = e; d += e; }
        float inv = 1.f / d;
        for (int i = 0; i < sz; i++) s_alpha[i] *= inv;
    }
    __syncthreads();

    for (int c = tid; c < HID; c += 256) {
        float acc = 0.f;
        for (int i = 0; i < sz; i++)
            acc = fmaf(s_alpha[i], g_H[(size_t)(s0 + i) * PADC + c], acc);
        s_rep[c] = acc;
    }
    __syncthreads();

    for (int rr = w; rr < NREL; rr += 8) {
        float acc = 0.f;
        for (int c = lane; c < HID; c += 32) acc = fmaf(s_rep[c], rel_w[rr * HID + c], acc);
        #pragma unroll
        for (int o = 16; o; o >>= 1) acc += __shfl_xor_sync(0xffffffffu, acc, o);
        if (lane == 0) out[b * NREL + rr] = acc + rel_b[rr];
    }
}

// ---------------- launch ----------------
extern "C" void kernel_launch(void* const* d_in, const int* in_sizes, int n_in,
                              void* d_out, int out_size) {
    const int*   X        = (const int*)  d_in[0];
    const int*   P1       = (const int*)  d_in[1];
    const int*   P2       = (const int*)  d_in[2];
    // d_in[3] mask, d_in[4] length: unused
    const int*   scope    = (const int*)  d_in[5];
    const int*   relation = (const int*)  d_in[6];
    const float* word_emb = (const float*)d_in[7];
    const float* p1e      = (const float*)d_in[8];
    const float* p2e      = (const float*)d_in[9];
    const float* conv_w   = (const float*)d_in[10];
    const float* conv_b   = (const float*)d_in[11];
    const float* rel_w    = (const float*)d_in[12];
    const float* rel_b    = (const float*)d_in[13];
    float* out = (float*)d_out;

    k_prep_B<<<(VEC_DIM * ROWW + 255) / 256, 256>>>(conv_w);
    k_pos_tables<<<NPOS, ROWW>>>(p1e, p2e, conv_w);
    k_build_word<<<(VOCAB + 31) / 32, 192>>>(word_emb);
    k_main<<<NSENT / 2, 128>>>(X, P1, P2, conv_b);
    k_bags<<<NBAG, 256>>>(scope, relation, rel_w, rel_b, out);
}

// round 4
// speedup vs baseline: 1.4993x; 1.2609x over previous
#include <cuda_runtime.h>
#include <cuda_fp16.h>

// ---------------- problem constants ----------------
#define NSENT   4000
#define LSEQ    128
#define VOCAB   50002
#define VEC_DIM 50
#define POS_DIM 5
#define EMB     60
#define HID     230
#define PADC    240            // HID padded to 240
#define ROWW    (3*PADC)       // 720 entries per table row (3 kernel taps)
#define NPOS    201
#define NBAG    500
#define NREL    25

// ---------------- device scratch (static; no runtime allocation) ----------------
__device__ float  g_B  [VEC_DIM * ROWW];           // transposed word-part weights [50][720]
__device__ __half g_Tw [(size_t)VOCAB * ROWW];     // word projection table (fp16, ~72 MB: L2-resident)
__device__ __half g_Tp1[NPOS * ROWW];              // pos1 projection table (fp16, 289 KB)
__device__ __half g_Tp2[NPOS * ROWW];              // pos2 projection table (fp16, 289 KB)
__device__ float  g_H  [NSENT * PADC];             // sentence encodings (post max-pool/relu)

// ---------------- helpers ----------------
__device__ __forceinline__ float4 add4(float4 a, float4 b) {
    return make_float4(a.x+b.x, a.y+b.y, a.z+b.z, a.w+b.w);
}
__device__ __forceinline__ float4 max4(float4 a, float4 b) {
    return make_float4(fmaxf(a.x,b.x), fmaxf(a.y,b.y), fmaxf(a.z,b.z), fmaxf(a.w,b.w));
}
__device__ __forceinline__ uint2 ldu2(const __half* p) {
    return *reinterpret_cast<const uint2*>(p);
}
// widen packed 4xfp16 (uint2) to float4
__device__ __forceinline__ float4 h4f(uint2 u) {
    __half2 lo = *reinterpret_cast<__half2*>(&u.x);
    __half2 hi = *reinterpret_cast<__half2*>(&u.y);
    float2 f0 = __half22float2(lo);
    float2 f1 = __half22float2(hi);
    return make_float4(f0.x, f0.y, f1.x, f1.y);
}
// sum of three packed-half quads, widened to fp32
__device__ __forceinline__ float4 sum3h(uint2 a, uint2 b, uint2 c) {
    return add4(add4(h4f(a), h4f(b)), h4f(c));
}

// packed f32x2 FMA: d = a*b + d
#define FMA2(d, a, b) \
    asm("fma.rn.f32x2 %0, %1, %2, %3;" : "=l"(d) : "l"(a), "l"(b), "l"(d))

// ---------------- kernel 1: transpose conv_w word-part into g_B ----------------
__global__ void k_prep_B(const float* __restrict__ conv_w) {
    int i = blockIdx.x * blockDim.x + threadIdx.x;
    if (i >= VEC_DIM * ROWW) return;
    int e = i / ROWW;
    int r = i - e * ROWW;
    int k = r / PADC;
    int c = r - k * PADC;
    g_B[i] = (c < HID) ? conv_w[(c * EMB + e) * 3 + k] : 0.f;
}

// ---------------- kernel 2: tiny pos tables (K=5, fp16 out) ----------------
__global__ void k_pos_tables(const float* __restrict__ p1e,
                             const float* __restrict__ p2e,
                             const float* __restrict__ conv_w) {
    int p = blockIdx.x;        // 0..200
    int r = threadIdx.x;       // 0..719
    int k = r / PADC;
    int c = r - k * PADC;
    float a1 = 0.f, a2 = 0.f;
    if (c < HID) {
        #pragma unroll
        for (int e = 0; e < POS_DIM; e++) {
            float w1 = conv_w[(c * EMB + VEC_DIM + e) * 3 + k];
            float w2 = conv_w[(c * EMB + VEC_DIM + POS_DIM + e) * 3 + k];
            a1 = fmaf(p1e[p * POS_DIM + e], w1, a1);
            a2 = fmaf(p2e[p * POS_DIM + e], w2, a2);
        }
    }
    g_Tp1[p * ROWW + r] = __float2half_rn(a1);
    g_Tp2[p * ROWW + r] = __float2half_rn(a2);
}

// ---------------- kernel 3: word table build GEMM (f32x2 packed, fp16 out) ----------------
__global__ __launch_bounds__(192) void k_build_word(const float* __restrict__ word_emb) {
    __shared__ unsigned long long s_a[32][VEC_DIM];   // (a,a) packed pairs
    int row0 = blockIdx.x * 32;
    for (int i = threadIdx.x; i < 32 * VEC_DIM; i += blockDim.x) {
        int r = i / VEC_DIM, e = i - r * VEC_DIM;
        int gr = row0 + r;
        float v = (gr < VOCAB) ? word_emb[gr * VEC_DIM + e] : 0.f;
        unsigned bi = __float_as_uint(v);
        s_a[r][e] = ((unsigned long long)bi << 32) | (unsigned long long)bi;
    }
    __syncthreads();
    int t = threadIdx.x;
    if (t >= 180) return;
    int col = t * 4;
    #pragma unroll
    for (int chunk = 0; chunk < 4; chunk++) {
        int rbase = chunk * 8;
        unsigned long long acc[8][2];
        #pragma unroll
        for (int r = 0; r < 8; r++) { acc[r][0] = 0ULL; acc[r][1] = 0ULL; }
        for (int e = 0; e < VEC_DIM; e++) {
            ulonglong2 b = *reinterpret_cast<const ulonglong2*>(&g_B[e * ROWW + col]);
            #pragma unroll
            for (int r = 0; r < 8; r++) {
                unsigned long long a = s_a[rbase + r][e];
                FMA2(acc[r][0], a, b.x);
                FMA2(acc[r][1], a, b.y);
            }
        }
        #pragma unroll
        for (int r = 0; r < 8; r++) {
            int gr = row0 + rbase + r;
            if (gr < VOCAB) {
                float lo0, hi0, lo1, hi1;
                asm("mov.b64 {%0, %1}, %2;" : "=f"(lo0), "=f"(hi0) : "l"(acc[r][0]));
                asm("mov.b64 {%0, %1}, %2;" : "=f"(lo1), "=f"(hi1) : "l"(acc[r][1]));
                __half2 h01 = __floats2half2_rn(lo0, hi0);
                __half2 h23 = __floats2half2_rn(lo1, hi1);
                uint2 st;
                st.x = *reinterpret_cast<unsigned*>(&h01);
                st.y = *reinterpret_cast<unsigned*>(&h23);
                *reinterpret_cast<uint2*>(&g_Tw[(size_t)gr * ROWW + col]) = st;
            }
        }
    }
}

// ---------------- kernel 4: main fused conv-via-gather + maxpool + relu ----------------
// block = 128 threads = 2 sentences x 64 lanes; lane tc<60 owns 4 channels
__global__ __launch_bounds__(128, 10) void k_main(const int* __restrict__ X,
                                                  const int* __restrict__ P1,
                                                  const int* __restrict__ P2,
                                                  const float* __restrict__ conv_b) {
    __shared__ int   s_idx[2][3][LSEQ];
    __shared__ float s_b[PADC];
    int tid = threadIdx.x;
    int grp = tid >> 6, tc = tid & 63;
    int sent0 = blockIdx.x * 2;

    for (int i = tid; i < 2 * LSEQ; i += 128) {
        int g = i >> 7, t = i & (LSEQ - 1);
        int s = sent0 + g;
        s_idx[g][0][t] = X [s * LSEQ + t];
        s_idx[g][1][t] = P1[s * LSEQ + t];
        s_idx[g][2][t] = P2[s * LSEQ + t];
    }
    for (int i = tid; i < PADC; i += 128) s_b[i] = (i < HID) ? conv_b[i] : 0.f;
    __syncthreads();

    if (tc >= 60) return;
    int coff = tc * 4;

    const int* xw = s_idx[grp][0];
    const int* x1 = s_idx[grp][1];
    const int* x2 = s_idx[grp][2];

    float4 maxv  = make_float4(-1e30f, -1e30f, -1e30f, -1e30f);
    float4 pend  = make_float4(0.f, 0.f, 0.f, 0.f);   // a0(t-1)+a1(t) carried forward
    float4 prev0 = make_float4(0.f, 0.f, 0.f, 0.f);   // a0 of previous token

    #pragma unroll 2
    for (int t = 0; t < LSEQ; t++) {
        const __half* rw = g_Tw  + (size_t)xw[t] * ROWW + coff;
        const __half* r1 = g_Tp1 + (size_t)x1[t] * ROWW + coff;
        const __half* r2 = g_Tp2 + (size_t)x2[t] * ROWW + coff;
        // issue all 9 8-byte loads before any math (short live ranges, max MLP)
        uint2 w0 = ldu2(rw);  uint2 w1 = ldu2(rw + PADC);  uint2 w2 = ldu2(rw + 2*PADC);
        uint2 q0 = ldu2(r1);  uint2 q1 = ldu2(r1 + PADC);  uint2 q2 = ldu2(r1 + 2*PADC);
        uint2 v0 = ldu2(r2);  uint2 v1 = ldu2(r2 + PADC);  uint2 v2 = ldu2(r2 + 2*PADC);

        float4 a2 = sum3h(w2, q2, v2);
        if (t > 0) {                      // finalize h[t-1] = a0(t-2)+a1(t-1)+a2(t)
            maxv = max4(maxv, add4(pend, a2));
        }
        float4 a1 = sum3h(w1, q1, v1);
        pend  = add4(prev0, a1);
        prev0 = sum3h(w0, q0, v0);
    }
    maxv = max4(maxv, pend);              // h[L-1] (a2 of token L is zero pad)

    int s = sent0 + grp;
    g_H[s * PADC + coff + 0] = fmaxf(maxv.x + s_b[coff + 0], 0.f);
    g_H[s * PADC + coff + 1] = fmaxf(maxv.y + s_b[coff + 1], 0.f);
    g_H[s * PADC + coff + 2] = fmaxf(maxv.z + s_b[coff + 2], 0.f);
    g_H[s * PADC + coff + 3] = fmaxf(maxv.w + s_b[coff + 3], 0.f);
}

// ---------------- kernel 5: per-bag softmax attention + classifier ----------------
__global__ __launch_bounds__(256) void k_bags(const int* __restrict__ scope,
                                              const int* __restrict__ relation,
                                              const float* __restrict__ rel_w,
                                              const float* __restrict__ rel_b,
                                              float* __restrict__ out) {
    int b = blockIdx.x;
    __shared__ float s_q[HID];
    __shared__ float s_logit[8];
    __shared__ float s_alpha[8];
    __shared__ float s_rep[HID];

    int tid = threadIdx.x;
    int w = tid >> 5, lane = tid & 31;
    int s0 = scope[2 * b], s1 = scope[2 * b + 1];
    int sz = s1 - s0;
    if (sz > 8) sz = 8;
    int rq = relation[b];

    for (int c = tid; c < HID; c += 256) s_q[c] = rel_w[rq * HID + c];
    __syncthreads();

    if (w < 8) {
        float acc = 0.f;
        if (w < sz) {
            const float* hp = g_H + (size_t)(s0 + w) * PADC;
            for (int c = lane; c < HID; c += 32) acc = fmaf(hp[c], s_q[c], acc);
        }
        #pragma unroll
        for (int o = 16; o; o >>= 1) acc += __shfl_xor_sync(0xffffffffu, acc, o);
        if (lane == 0) s_logit[w] = (w < sz) ? acc : -1e30f;
    }
    __syncthreads();

    if (tid == 0) {
        float m = -1e30f;
        for (int i = 0; i < sz; i++) m = fmaxf(m, s_logit[i]);
        float d = 0.f;
        for (int i = 0; i < sz; i++) { float e = expf(s_logit[i] - m); s_alpha[i] = e; d += e; }
        float inv = 1.f / d;
        for (int i = 0; i < sz; i++) s_alpha[i] *= inv;
    }
    __syncthreads();

    for (int c = tid; c < HID; c += 256) {
        float acc = 0.f;
        for (int i = 0; i < sz; i++)
            acc = fmaf(s_alpha[i], g_H[(size_t)(s0 + i) * PADC + c], acc);
        s_rep[c] = acc;
    }
    __syncthreads();

    for (int rr = w; rr < NREL; rr += 8) {
        float acc = 0.f;
        for (int c = lane; c < HID; c += 32) acc = fmaf(s_rep[c], rel_w[rr * HID + c], acc);
        #pragma unroll
        for (int o = 16; o; o >>= 1) acc += __shfl_xor_sync(0xffffffffu, acc, o);
        if (lane == 0) out[b * NREL + rr] = acc + rel_b[rr];
    }
}

// ---------------- launch ----------------
extern "C" void kernel_launch(void* const* d_in, const int* in_sizes, int n_in,
                              void* d_out, int out_size) {
    const int*   X        = (const int*)  d_in[0];
    const int*   P1       = (const int*)  d_in[1];
    const int*   P2       = (const int*)  d_in[2];
    // d_in[3] mask, d_in[4] length: unused
    const int*   scope    = (const int*)  d_in[5];
    const int*   relation = (const int*)  d_in[6];
    const float* word_emb = (const float*)d_in[7];
    const float* p1e      = (const float*)d_in[8];
    const float* p2e      = (const float*)d_in[9];
    const float* conv_w   = (const float*)d_in[10];
    const float* conv_b   = (const float*)d_in[11];
    const float* rel_w    = (const float*)d_in[12];
    const float* rel_b    = (const float*)d_in[13];
    float* out = (float*)d_out;

    k_prep_B<<<(VEC_DIM * ROWW + 255) / 256, 256>>>(conv_w);
    k_pos_tables<<<NPOS, ROWW>>>(p1e, p2e, conv_w);
    k_build_word<<<(VOCAB + 31) / 32, 192>>>(word_emb);
    k_main<<<NSENT / 2, 128>>>(X, P1, P2, conv_b);
    k_bags<<<NBAG, 256>>>(scope, relation, rel_w, rel_b, out);
}

// round 5
// speedup vs baseline: 1.6988x; 1.1330x over previous
#include <cuda_runtime.h>
#include <cuda_fp16.h>

// ---------------- problem constants ----------------
#define NSENT   4000
#define LSEQ    128
#define VOCAB   50002
#define VEC_DIM 50
#define POS_DIM 5
#define EMB     60
#define HID     230
#define PADC    240            // HID padded to 240
#define ROWW    (3*PADC)       // 720 entries per table row (3 kernel taps)
#define KPAD    64             // VEC_DIM padded to 64 for mma (4 k-steps of 16)
#define NCOLT   (ROWW/8)       // 90 col-tiles of 8
#define NROWT   ((VOCAB+15)/16)// 3126 row-tiles of 16
#define NPOS    201
#define NBAG    500
#define NREL    25

// ---------------- device scratch (static; no runtime allocation) ----------------
__device__ __half g_Bt [ROWW * KPAD];              // B transposed: [720 cols][64 k] fp16 (92 KB)
__device__ __half g_Tw [(size_t)VOCAB * ROWW];     // word projection table (fp16, ~72 MB)
__device__ __half g_Tp1[NPOS * ROWW];              // pos1 projection table (fp16)
__device__ __half g_Tp2[NPOS * ROWW];              // pos2 projection table (fp16)
__device__ float  g_H  [NSENT * PADC];             // sentence encodings

// ---------------- helpers ----------------
__device__ __forceinline__ uint2 ldu2(const __half* p) {
    return *reinterpret_cast<const uint2*>(p);
}
__device__ __forceinline__ __half2 h2lo(uint2 u) { return *reinterpret_cast<__half2*>(&u.x); }
__device__ __forceinline__ __half2 h2hi(uint2 u) { return *reinterpret_cast<__half2*>(&u.y); }

// ---------------- kernel 1: build fp16 transposed weight matrix g_Bt ----------------
// g_Bt[n][k] = conv_w[c][k][tap],  n = tap*PADC + c   (zero pad c>=HID, k>=VEC_DIM)
__global__ void k_prep_Bt(const float* __restrict__ conv_w) {
    int i = blockIdx.x * blockDim.x + threadIdx.x;
    if (i >= ROWW * KPAD) return;
    int n = i >> 6;            // 0..719
    int k = i & 63;
    int tap = n / PADC;
    int c = n - tap * PADC;
    float v = (c < HID && k < VEC_DIM) ? conv_w[(c * EMB + k) * 3 + tap] : 0.f;
    g_Bt[i] = __float2half_rn(v);
}

// ---------------- kernel 2: tiny pos tables (K=5, fp16 out) ----------------
__global__ void k_pos_tables(const float* __restrict__ p1e,
                             const float* __restrict__ p2e,
                             const float* __restrict__ conv_w) {
    int p = blockIdx.x;        // 0..200
    int r = threadIdx.x;       // 0..719
    int k = r / PADC;
    int c = r - k * PADC;
    float a1 = 0.f, a2 = 0.f;
    if (c < HID) {
        #pragma unroll
        for (int e = 0; e < POS_DIM; e++) {
            float w1 = conv_w[(c * EMB + VEC_DIM + e) * 3 + k];
            float w2 = conv_w[(c * EMB + VEC_DIM + POS_DIM + e) * 3 + k];
            a1 = fmaf(p1e[p * POS_DIM + e], w1, a1);
            a2 = fmaf(p2e[p * POS_DIM + e], w2, a2);
        }
    }
    g_Tp1[p * ROWW + r] = __float2half_rn(a1);
    g_Tp2[p * ROWW + r] = __float2half_rn(a2);
}

// ---------------- kernel 3: word table build via mma.sync (HMMA, fp32 accum) ----------------
// Each block: one 16-row vocab strip. 8 warps split 90 col-tiles (8 cols each).
// D[16,720] = A[16,64(fp16)] x B[64,720(fp16)], stored fp16.
__global__ __launch_bounds__(256) void k_build_word(const float* __restrict__ word_emb) {
    __shared__ __half s_A[16 * 66];                 // 16 rows x 64 k, stride 66 (conflict pad)
    int row0 = blockIdx.x * 16;
    int tid  = threadIdx.x;

    // stage A strip fp32 -> fp16 (zero pad k>=50, row>=VOCAB)
    for (int i = tid; i < 16 * 64; i += 256) {
        int r = i >> 6, k = i & 63;
        int gr = row0 + r;
        float v = (gr < VOCAB && k < VEC_DIM) ? word_emb[gr * VEC_DIM + k] : 0.f;
        s_A[r * 66 + k] = __float2half_rn(v);
    }
    __syncthreads();

    int warp = tid >> 5, lane = tid & 31;
    int g = lane >> 2, t = lane & 3;

    // A fragments for 4 k-steps, held in registers (reused across all col-tiles)
    unsigned uA[4][4];
    #pragma unroll
    for (int ks = 0; ks < 4; ks++) {
        int k0 = ks * 16;
        uA[ks][0] = *reinterpret_cast<unsigned*>(&s_A[ g      * 66 + k0 + 2*t    ]);
        uA[ks][1] = *reinterpret_cast<unsigned*>(&s_A[(g + 8) * 66 + k0 + 2*t    ]);
        uA[ks][2] = *reinterpret_cast<unsigned*>(&s_A[ g      * 66 + k0 + 2*t + 8]);
        uA[ks][3] = *reinterpret_cast<unsigned*>(&s_A[(g + 8) * 66 + k0 + 2*t + 8]);
    }

    int r0 = row0 + g;
    int r1 = row0 + g + 8;

    for (int ct = warp; ct < NCOLT; ct += 8) {
        int n0 = ct * 8;
        float c0 = 0.f, c1 = 0.f, c2 = 0.f, c3 = 0.f;
        #pragma unroll
        for (int ks = 0; ks < 4; ks++) {
            int k0 = ks * 16;
            const __half* bp = g_Bt + (n0 + g) * KPAD + k0 + 2*t;
            unsigned b0 = *reinterpret_cast<const unsigned*>(bp);      // k=2t,2t+1
            unsigned b1 = *reinterpret_cast<const unsigned*>(bp + 8);  // k=2t+8,2t+9
            asm volatile(
                "mma.sync.aligned.m16n8k16.row.col.f32.f16.f16.f32 "
                "{%0,%1,%2,%3}, {%4,%5,%6,%7}, {%8,%9}, {%0,%1,%2,%3};"
                : "+f"(c0), "+f"(c1), "+f"(c2), "+f"(c3)
                : "r"(uA[ks][0]), "r"(uA[ks][1]), "r"(uA[ks][2]), "r"(uA[ks][3]),
                  "r"(b0), "r"(b1));
        }
        int col = n0 + 2*t;
        if (r0 < VOCAB) {
            __half2 h = __floats2half2_rn(c0, c1);
            *reinterpret_cast<__half2*>(&g_Tw[(size_t)r0 * ROWW + col]) = h;
        }
        if (r1 < VOCAB) {
            __half2 h = __floats2half2_rn(c2, c3);
            *reinterpret_cast<__half2*>(&g_Tw[(size_t)r1 * ROWW + col]) = h;
        }
    }
}

// ---------------- kernel 4: main fused conv-via-gather + maxpool + relu (half2 math) ----------------
// block = 128 threads = 2 sentences x 64 lanes; lane tc<60 owns 4 channels (2 half2)
__global__ __launch_bounds__(128, 10) void k_main(const int* __restrict__ X,
                                                  const int* __restrict__ P1,
                                                  const int* __restrict__ P2,
                                                  const float* __restrict__ conv_b) {
    __shared__ int   s_idx[2][3][LSEQ];
    __shared__ float s_b[PADC];
    int tid = threadIdx.x;
    int grp = tid >> 6, tc = tid & 63;
    int sent0 = blockIdx.x * 2;

    for (int i = tid; i < 2 * LSEQ; i += 128) {
        int g = i >> 7, t = i & (LSEQ - 1);
        int s = sent0 + g;
        s_idx[g][0][t] = X [s * LSEQ + t];
        s_idx[g][1][t] = P1[s * LSEQ + t];
        s_idx[g][2][t] = P2[s * LSEQ + t];
    }
    for (int i = tid; i < PADC; i += 128) s_b[i] = (i < HID) ? conv_b[i] : 0.f;
    __syncthreads();

    if (tc >= 60) return;
    int coff = tc * 4;

    const int* xw = s_idx[grp][0];
    const int* x1 = s_idx[grp][1];
    const int* x2 = s_idx[grp][2];

    const __half2 z2 = __float2half2_rn(0.f);
    __half2 maxA = __float2half2_rn(-60000.f), maxB = maxA;
    __half2 pendA = z2, pendB = z2;     // a0(t-1)+a1(t) carried forward
    __half2 prevA = z2, prevB = z2;     // a0 of previous token

    #pragma unroll 2
    for (int t = 0; t < LSEQ; t++) {
        const __half* rw = g_Tw  + (size_t)xw[t] * ROWW + coff;
        const __half* r1 = g_Tp1 + (size_t)x1[t] * ROWW + coff;
        const __half* r2 = g_Tp2 + (size_t)x2[t] * ROWW + coff;
        // issue all 9 8-byte loads up front
        uint2 w0 = ldu2(rw);  uint2 w1 = ldu2(rw + PADC);  uint2 w2 = ldu2(rw + 2*PADC);
        uint2 q0 = ldu2(r1);  uint2 q1 = ldu2(r1 + PADC);  uint2 q2 = ldu2(r1 + 2*PADC);
        uint2 v0 = ldu2(r2);  uint2 v1 = ldu2(r2 + PADC);  uint2 v2 = ldu2(r2 + 2*PADC);

        __half2 a2A = __hadd2(__hadd2(h2lo(w2), h2lo(q2)), h2lo(v2));
        __half2 a2B = __hadd2(__hadd2(h2hi(w2), h2hi(q2)), h2hi(v2));
        if (t > 0) {                  // finalize h[t-1] = a0(t-2)+a1(t-1)+a2(t)
            maxA = __hmax2(maxA, __hadd2(pendA, a2A));
            maxB = __hmax2(maxB, __hadd2(pendB, a2B));
        }
        __half2 a1A = __hadd2(__hadd2(h2lo(w1), h2lo(q1)), h2lo(v1));
        __half2 a1B = __hadd2(__hadd2(h2hi(w1), h2hi(q1)), h2hi(v1));
        pendA = __hadd2(prevA, a1A);
        pendB = __hadd2(prevB, a1B);
        prevA = __hadd2(__hadd2(h2lo(w0), h2lo(q0)), h2lo(v0));
        prevB = __hadd2(__hadd2(h2hi(w0), h2hi(q0)), h2hi(v0));
    }
    maxA = __hmax2(maxA, pendA);      // h[L-1] (a2 of token L is zero pad)
    maxB = __hmax2(maxB, pendB);

    float2 mA = __half22float2(maxA);
    float2 mB = __half22float2(maxB);
    int s = sent0 + grp;
    g_H[s * PADC + coff + 0] = fmaxf(mA.x + s_b[coff + 0], 0.f);
    g_H[s * PADC + coff + 1] = fmaxf(mA.y + s_b[coff + 1], 0.f);
    g_H[s * PADC + coff + 2] = fmaxf(mB.x + s_b[coff + 2], 0.f);
    g_H[s * PADC + coff + 3] = fmaxf(mB.y + s_b[coff + 3], 0.f);
}

// ---------------- kernel 5: per-bag softmax attention + classifier ----------------
__global__ __launch_bounds__(256) void k_bags(const int* __restrict__ scope,
                                              const int* __restrict__ relation,
                                              const float* __restrict__ rel_w,
                                              const float* __restrict__ rel_b,
                                              float* __restrict__ out) {
    int b = blockIdx.x;
    __shared__ float s_q[HID];
    __shared__ float s_logit[8];
    __shared__ float s_alpha[8];
    __shared__ float s_rep[HID];

    int tid = threadIdx.x;
    int w = tid >> 5, lane = tid & 31;
    int s0 = scope[2 * b], s1 = scope[2 * b + 1];
    int sz = s1 - s0;
    if (sz > 8) sz = 8;
    int rq = relation[b];

    for (int c = tid; c < HID; c += 256) s_q[c] = rel_w[rq * HID + c];
    __syncthreads();

    if (w < 8) {
        float acc = 0.f;
        if (w < sz) {
            const float* hp = g_H + (size_t)(s0 + w) * PADC;
            for (int c = lane; c < HID; c += 32) acc = fmaf(hp[c], s_q[c], acc);
        }
        #pragma unroll
        for (int o = 16; o; o >>= 1) acc += __shfl_xor_sync(0xffffffffu, acc, o);
        if (lane == 0) s_logit[w] = (w < sz) ? acc : -1e30f;
    }
    __syncthreads();

    if (tid == 0) {
        float m = -1e30f;
        for (int i = 0; i < sz; i++) m = fmaxf(m, s_logit[i]);
        float d = 0.f;
        for (int i = 0; i < sz; i++) { float e = expf(s_logit[i] - m); s_alpha[i] = e; d += e; }
        float inv = 1.f / d;
        for (int i = 0; i < sz; i++) s_alpha[i] *= inv;
    }
    __syncthreads();

    for (int c = tid; c < HID; c += 256) {
        float acc = 0.f;
        for (int i = 0; i < sz; i++)
            acc = fmaf(s_alpha[i], g_H[(size_t)(s0 + i) * PADC + c], acc);
        s_rep[c] = acc;
    }
    __syncthreads();

    for (int rr = w; rr < NREL; rr += 8) {
        float acc = 0.f;
        for (int c = lane; c < HID; c += 32) acc = fmaf(s_rep[c], rel_w[rr * HID + c], acc);
        #pragma unroll
        for (int o = 16; o; o >>= 1) acc += __shfl_xor_sync(0xffffffffu, acc, o);
        if (lane == 0) out[b * NREL + rr] = acc + rel_b[rr];
    }
}

// ---------------- launch ----------------
extern "C" void kernel_launch(void* const* d_in, const int* in_sizes, int n_in,
                              void* d_out, int out_size) {
    const int*   X        = (const int*)  d_in[0];
    const int*   P1       = (const int*)  d_in[1];
    const int*   P2       = (const int*)  d_in[2];
    // d_in[3] mask, d_in[4] length: unused
    const int*   scope    = (const int*)  d_in[5];
    const int*   relation = (const int*)  d_in[6];
    const float* word_emb = (const float*)d_in[7];
    const float* p1e      = (const float*)d_in[8];
    const float* p2e      = (const float*)d_in[9];
    const float* conv_w   = (const float*)d_in[10];
    const float* conv_b   = (const float*)d_in[11];
    const float* rel_w    = (const float*)d_in[12];
    const float* rel_b    = (const float*)d_in[13];
    float* out = (float*)d_out;

    k_prep_Bt<<<(ROWW * KPAD + 255) / 256, 256>>>(conv_w);
    k_pos_tables<<<NPOS, ROWW>>>(p1e, p2e, conv_w);
    k_build_word<<<NROWT, 256>>>(word_emb);
    k_main<<<NSENT / 2, 128>>>(X, P1, P2, conv_b);
    k_bags<<<NBAG, 256>>>(scope, relation, rel_w, rel_b, out);
}

// round 6
// speedup vs baseline: 1.8941x; 1.1150x over previous
#include <cuda_runtime.h>
#include <cuda_fp16.h>

// ---------------- problem constants ----------------
#define NSENT   4000
#define LSEQ    128
#define VOCAB   50002
#define VEC_DIM 50
#define POS_DIM 5
#define EMB     60
#define HID     230
#define PADC    240            // HID padded to 240
#define ROWW    (3*PADC)       // 720 entries per table row (3 kernel taps)
#define ROWB    (ROWW*2)       // row stride in bytes (fp16)
#define KPAD    64             // VEC_DIM padded to 64 for mma (4 k-steps of 16)
#define NCOLT   (ROWW/8)       // 90 col-tiles of 8
#define NROWT   ((VOCAB+15)/16)// 3126 row-tiles of 16
#define NPOS    201
#define NBAG    500
#define NREL    25

// ---------------- device scratch (static; no runtime allocation) ----------------
__device__ __half g_Bt [ROWW * KPAD];              // B transposed: [720 cols][64 k] fp16 (92 KB)
__device__ __half g_Tw [(size_t)VOCAB * ROWW];     // word projection table (fp16, ~72 MB)
__device__ __half g_Tp1[NPOS * ROWW];              // pos1 projection table (fp16)
__device__ __half g_Tp2[NPOS * ROWW];              // pos2 projection table (fp16)
__device__ float  g_H  [NSENT * PADC];             // sentence encodings

// ---------------- helpers ----------------
__device__ __forceinline__ uint2 ldu2b(const char* p) {
    return *reinterpret_cast<const uint2*>(p);
}
__device__ __forceinline__ __half2 h2lo(uint2 u) { return *reinterpret_cast<__half2*>(&u.x); }
__device__ __forceinline__ __half2 h2hi(uint2 u) { return *reinterpret_cast<__half2*>(&u.y); }

// ---------------- kernel 1: build fp16 transposed weight matrix g_Bt ----------------
__global__ void k_prep_Bt(const float* __restrict__ conv_w) {
    int i = blockIdx.x * blockDim.x + threadIdx.x;
    if (i >= ROWW * KPAD) return;
    int n = i >> 6;            // 0..719
    int k = i & 63;
    int tap = n / PADC;
    int c = n - tap * PADC;
    float v = (c < HID && k < VEC_DIM) ? conv_w[(c * EMB + k) * 3 + tap] : 0.f;
    g_Bt[i] = __float2half_rn(v);
}

// ---------------- kernel 2: tiny pos tables (K=5, fp16 out) ----------------
__global__ void k_pos_tables(const float* __restrict__ p1e,
                             const float* __restrict__ p2e,
                             const float* __restrict__ conv_w) {
    int p = blockIdx.x;        // 0..200
    int r = threadIdx.x;       // 0..719
    int k = r / PADC;
    int c = r - k * PADC;
    float a1 = 0.f, a2 = 0.f;
    if (c < HID) {
        #pragma unroll
        for (int e = 0; e < POS_DIM; e++) {
            float w1 = conv_w[(c * EMB + VEC_DIM + e) * 3 + k];
            float w2 = conv_w[(c * EMB + VEC_DIM + POS_DIM + e) * 3 + k];
            a1 = fmaf(p1e[p * POS_DIM + e], w1, a1);
            a2 = fmaf(p2e[p * POS_DIM + e], w2, a2);
        }
    }
    g_Tp1[p * ROWW + r] = __float2half_rn(a1);
    g_Tp2[p * ROWW + r] = __float2half_rn(a2);
}

// ---------------- kernel 3: word table build via mma.sync (HMMA, fp32 accum) ----------------
__global__ __launch_bounds__(256) void k_build_word(const float* __restrict__ word_emb) {
    __shared__ __half s_A[16 * 66];
    int row0 = blockIdx.x * 16;
    int tid  = threadIdx.x;

    for (int i = tid; i < 16 * 64; i += 256) {
        int r = i >> 6, k = i & 63;
        int gr = row0 + r;
        float v = (gr < VOCAB && k < VEC_DIM) ? word_emb[gr * VEC_DIM + k] : 0.f;
        s_A[r * 66 + k] = __float2half_rn(v);
    }
    __syncthreads();

    int warp = tid >> 5, lane = tid & 31;
    int g = lane >> 2, t = lane & 3;

    unsigned uA[4][4];
    #pragma unroll
    for (int ks = 0; ks < 4; ks++) {
        int k0 = ks * 16;
        uA[ks][0] = *reinterpret_cast<unsigned*>(&s_A[ g      * 66 + k0 + 2*t    ]);
        uA[ks][1] = *reinterpret_cast<unsigned*>(&s_A[(g + 8) * 66 + k0 + 2*t    ]);
        uA[ks][2] = *reinterpret_cast<unsigned*>(&s_A[ g      * 66 + k0 + 2*t + 8]);
        uA[ks][3] = *reinterpret_cast<unsigned*>(&s_A[(g + 8) * 66 + k0 + 2*t + 8]);
    }

    int r0 = row0 + g;
    int r1 = row0 + g + 8;

    for (int ct = warp; ct < NCOLT; ct += 8) {
        int n0 = ct * 8;
        float c0 = 0.f, c1 = 0.f, c2 = 0.f, c3 = 0.f;
        #pragma unroll
        for (int ks = 0; ks < 4; ks++) {
            int k0 = ks * 16;
            const __half* bp = g_Bt + (n0 + g) * KPAD + k0 + 2*t;
            unsigned b0 = *reinterpret_cast<const unsigned*>(bp);
            unsigned b1 = *reinterpret_cast<const unsigned*>(bp + 8);
            asm volatile(
                "mma.sync.aligned.m16n8k16.row.col.f32.f16.f16.f32 "
                "{%0,%1,%2,%3}, {%4,%5,%6,%7}, {%8,%9}, {%0,%1,%2,%3};"
                : "+f"(c0), "+f"(c1), "+f"(c2), "+f"(c3)
                : "r"(uA[ks][0]), "r"(uA[ks][1]), "r"(uA[ks][2]), "r"(uA[ks][3]),
                  "r"(b0), "r"(b1));
        }
        int col = n0 + 2*t;
        if (r0 < VOCAB) {
            __half2 h = __floats2half2_rn(c0, c1);
            *reinterpret_cast<__half2*>(&g_Tw[(size_t)r0 * ROWW + col]) = h;
        }
        if (r1 < VOCAB) {
            __half2 h = __floats2half2_rn(c2, c3);
            *reinterpret_cast<__half2*>(&g_Tw[(size_t)r1 * ROWW + col]) = h;
        }
    }
}

// ---------------- kernel 4: main fused conv-via-gather + maxpool + relu ----------------
// half2 math + 1-deep register prefetch pipeline (loads for t+1 issued before compute of t)
// block = 128 threads = 2 sentences x 64 lanes; lane tc<60 owns 4 channels
__global__ __launch_bounds__(128, 8) void k_main(const int* __restrict__ X,
                                                 const int* __restrict__ P1,
                                                 const int* __restrict__ P2,
                                                 const float* __restrict__ conv_b) {
    __shared__ int   s_off[2][3][LSEQ + 1];   // precomputed BYTE offsets (+1 dummy token)
    __shared__ float s_b[PADC];
    int tid = threadIdx.x;
    int grp = tid >> 6, tc = tid & 63;
    int sent0 = blockIdx.x * 2;

    for (int i = tid; i < 2 * LSEQ; i += 128) {
        int g = i >> 7, t = i & (LSEQ - 1);
        int s = sent0 + g;
        s_off[g][0][t] = X [s * LSEQ + t] * ROWB;
        s_off[g][1][t] = P1[s * LSEQ + t] * ROWB;
        s_off[g][2][t] = P2[s * LSEQ + t] * ROWB;
    }
    if (tid < 2) {                          // dummy token for prefetch overrun
        s_off[tid][0][LSEQ] = 0;
        s_off[tid][1][LSEQ] = 0;
        s_off[tid][2][LSEQ] = 0;
    }
    for (int i = tid; i < PADC; i += 128) s_b[i] = (i < HID) ? conv_b[i] : 0.f;
    __syncthreads();

    if (tc >= 60) return;
    int cb = tc * 8;                        // channel byte offset within row

    const int* ow = s_off[grp][0];
    const int* o1 = s_off[grp][1];
    const int* o2 = s_off[grp][2];
    const char* baseW = (const char*)g_Tw  + cb;
    const char* base1 = (const char*)g_Tp1 + cb;
    const char* base2 = (const char*)g_Tp2 + cb;

    // pend init very negative: absorbs the t=0 max-update without a branch.
    __half2 maxA  = __float2half2_rn(-60000.f), maxB = maxA;
    __half2 pendA = __float2half2_rn(-16384.f), pendB = pendA;
    __half2 prevA = __float2half2_rn(0.f),      prevB = prevA;

    // prologue: load t=0
    const char* rw = baseW + ow[0];
    const char* r1 = base1 + o1[0];
    const char* r2 = base2 + o2[0];
    uint2 w0 = ldu2b(rw);  uint2 w1 = ldu2b(rw + 2*PADC);  uint2 w2 = ldu2b(rw + 4*PADC);
    uint2 q0 = ldu2b(r1);  uint2 q1 = ldu2b(r1 + 2*PADC);  uint2 q2 = ldu2b(r1 + 4*PADC);
    uint2 v0 = ldu2b(r2);  uint2 v1 = ldu2b(r2 + 2*PADC);  uint2 v2 = ldu2b(r2 + 4*PADC);

    #pragma unroll 4
    for (int t = 0; t < LSEQ; t++) {
        // issue loads for t+1 (dummy row 0 at t=LSEQ-1 -> values unused)
        const char* nw = baseW + ow[t + 1];
        const char* n1 = base1 + o1[t + 1];
        const char* n2 = base2 + o2[t + 1];
        uint2 W0 = ldu2b(nw);  uint2 W1 = ldu2b(nw + 2*PADC);  uint2 W2 = ldu2b(nw + 4*PADC);
        uint2 Q0 = ldu2b(n1);  uint2 Q1 = ldu2b(n1 + 2*PADC);  uint2 Q2 = ldu2b(n1 + 4*PADC);
        uint2 V0 = ldu2b(n2);  uint2 V1 = ldu2b(n2 + 2*PADC);  uint2 V2 = ldu2b(n2 + 4*PADC);

        // compute on t's registers
        __half2 a2A = __hadd2(__hadd2(h2lo(w2), h2lo(q2)), h2lo(v2));
        __half2 a2B = __hadd2(__hadd2(h2hi(w2), h2hi(q2)), h2hi(v2));
        maxA = __hmax2(maxA, __hadd2(pendA, a2A));      // h[t-1] (t=0: ~-16000, harmless)
        maxB = __hmax2(maxB, __hadd2(pendB, a2B));
        __half2 a1A = __hadd2(__hadd2(h2lo(w1), h2lo(q1)), h2lo(v1));
        __half2 a1B = __hadd2(__hadd2(h2hi(w1), h2hi(q1)), h2hi(v1));
        pendA = __hadd2(prevA, a1A);
        pendB = __hadd2(prevB, a1B);
        prevA = __hadd2(__hadd2(h2lo(w0), h2lo(q0)), h2lo(v0));
        prevB = __hadd2(__hadd2(h2hi(w0), h2hi(q0)), h2hi(v0));

        // rotate buffers
        w0 = W0; w1 = W1; w2 = W2;
        q0 = Q0; q1 = Q1; q2 = Q2;
        v0 = V0; v1 = V1; v2 = V2;
    }
    maxA = __hmax2(maxA, pendA);            // h[L-1] (a2 of pad token = 0)
    maxB = __hmax2(maxB, pendB);

    float2 mA = __half22float2(maxA);
    float2 mB = __half22float2(maxB);
    int s = sent0 + grp;
    int coff = tc * 4;
    g_H[s * PADC + coff + 0] = fmaxf(mA.x + s_b[coff + 0], 0.f);
    g_H[s * PADC + coff + 1] = fmaxf(mA.y + s_b[coff + 1], 0.f);
    g_H[s * PADC + coff + 2] = fmaxf(mB.x + s_b[coff + 2], 0.f);
    g_H[s * PADC + coff + 3] = fmaxf(mB.y + s_b[coff + 3], 0.f);
}

// ---------------- kernel 5: per-bag softmax attention + classifier ----------------
__global__ __launch_bounds__(256) void k_bags(const int* __restrict__ scope,
                                              const int* __restrict__ relation,
                                              const float* __restrict__ rel_w,
                                              const float* __restrict__ rel_b,
                                              float* __restrict__ out) {
    int b = blockIdx.x;
    __shared__ float s_q[HID];
    __shared__ float s_logit[8];
    __shared__ float s_alpha[8];
    __shared__ float s_rep[HID];

    int tid = threadIdx.x;
    int w = tid >> 5, lane = tid & 31;
    int s0 = scope[2 * b], s1 = scope[2 * b + 1];
    int sz = s1 - s0;
    if (sz > 8) sz = 8;
    int rq = relation[b];

    for (int c = tid; c < HID; c += 256) s_q[c] = rel_w[rq * HID + c];
    __syncthreads();

    if (w < 8) {
        float acc = 0.f;
        if (w < sz) {
            const float* hp = g_H + (size_t)(s0 + w) * PADC;
            for (int c = lane; c < HID; c += 32) acc = fmaf(hp[c], s_q[c], acc);
        }
        #pragma unroll
        for (int o = 16; o; o >>= 1) acc += __shfl_xor_sync(0xffffffffu, acc, o);
        if (lane == 0) s_logit[w] = (w < sz) ? acc : -1e30f;
    }
    __syncthreads();

    if (tid == 0) {
        float m = -1e30f;
        for (int i = 0; i < sz; i++) m = fmaxf(m, s_logit[i]);
        float d = 0.f;
        for (int i = 0; i < sz; i++) { float e = expf(s_logit[i] - m); s_alpha[i] = e; d += e; }
        float inv = 1.f / d;
        for (int i = 0; i < sz; i++) s_alpha[i] *= inv;
    }
    __syncthreads();

    for (int c = tid; c < HID; c += 256) {
        float acc = 0.f;
        for (int i = 0; i < sz; i++)
            acc = fmaf(s_alpha[i], g_H[(size_t)(s0 + i) * PADC + c], acc);
        s_rep[c] = acc;
    }
    __syncthreads();

    for (int rr = w; rr < NREL; rr += 8) {
        float acc = 0.f;
        for (int c = lane; c < HID; c += 32) acc = fmaf(s_rep[c], rel_w[rr * HID + c], acc);
        #pragma unroll
        for (int o = 16; o; o >>= 1) acc += __shfl_xor_sync(0xffffffffu, acc, o);
        if (lane == 0) out[b * NREL + rr] = acc + rel_b[rr];
    }
}

// ---------------- launch ----------------
extern "C" void kernel_launch(void* const* d_in, const int* in_sizes, int n_in,
                              void* d_out, int out_size) {
    const int*   X        = (const int*)  d_in[0];
    const int*   P1       = (const int*)  d_in[1];
    const int*   P2       = (const int*)  d_in[2];
    // d_in[3] mask, d_in[4] length: unused
    const int*   scope    = (const int*)  d_in[5];
    const int*   relation = (const int*)  d_in[6];
    const float* word_emb = (const float*)d_in[7];
    const float* p1e      = (const float*)d_in[8];
    const float* p2e      = (const float*)d_in[9];
    const float* conv_w   = (const float*)d_in[10];
    const float* conv_b   = (const float*)d_in[11];
    const float* rel_w    = (const float*)d_in[12];
    const float* rel_b    = (const float*)d_in[13];
    float* out = (float*)d_out;

    k_prep_Bt<<<(ROWW * KPAD + 255) / 256, 256>>>(conv_w);
    k_pos_tables<<<NPOS, ROWW>>>(p1e, p2e, conv_w);
    k_build_word<<<NROWT, 256>>>(word_emb);
    k_main<<<NSENT / 2, 128>>>(X, P1, P2, conv_b);
    k_bags<<<NBAG, 256>>>(scope, relation, rel_w, rel_b, out);
}